// round 1
// baseline (speedup 1.0000x reference)
#include <cuda_runtime.h>
#include <math.h>
#include <stdint.h>

// HashEmbedder: 16-level 2D multires hash grid, 2 feats/level, T=2^19.
// One thread per (point, level). 4 random float2 gathers + bilinear lerp.

#define NLEV 16
#define TLOG2 19
#define TSIZE (1u << TLOG2)
#define HMASK ((1u << TLOG2) - 1u)
#define PRIME1 2654435761u

struct ResParams {
    float res[NLEV];
};

__global__ __launch_bounds__(256) void hash_embed_kernel(
    const float* __restrict__ x,
    const float* __restrict__ emb,
    float* __restrict__ out,
    int n_points,
    ResParams rp)
{
    __shared__ float s_res[NLEV];
    if (threadIdx.x < NLEV) s_res[threadIdx.x] = rp.res[threadIdx.x];
    __syncthreads();

    int gid = blockIdx.x * blockDim.x + threadIdx.x;
    int p = gid >> 4;          // point index
    if (p >= n_points) return;
    int l = gid & 15;          // level index

    // 16 consecutive threads read the same point -> broadcast load
    float2 xy = __ldg(((const float2*)x) + p);

    float res = s_res[l];
    float px = xy.x * res;
    float py = xy.y * res;
    float fx = floorf(px);
    float fy = floorf(py);
    float wx = px - fx;
    float wy = py - fy;

    int ri  = (int)res;
    int ix  = (int)fx;
    int iy  = (int)fy;
    int ix0 = min(max(ix, 0), ri);
    int iy0 = min(max(iy, 0), ri);
    int ix1 = min(ix + 1, ri);   // ix+1 >= 1 > 0, no lower clamp needed
    int iy1 = min(iy + 1, ri);

    uint32_t ux0 = (uint32_t)ix0;
    uint32_t ux1 = (uint32_t)ix1;
    uint32_t yp0 = (uint32_t)iy0 * PRIME1;
    uint32_t yp1 = (uint32_t)iy1 * PRIME1;

    uint32_t a00 = (ux0 ^ yp0) & HMASK;
    uint32_t a10 = (ux1 ^ yp0) & HMASK;
    uint32_t a01 = (ux0 ^ yp1) & HMASK;
    uint32_t a11 = (ux1 ^ yp1) & HMASK;

    const float2* __restrict__ tab =
        ((const float2*)emb) + (size_t)l * (size_t)TSIZE;

    float2 f00 = __ldg(tab + a00);
    float2 f10 = __ldg(tab + a10);
    float2 f01 = __ldg(tab + a01);
    float2 f11 = __ldg(tab + a11);

    float u = 1.0f - wx;
    float v = 1.0f - wy;

    float2 o;
    o.x = (f00.x * u + f10.x * wx) * v + (f01.x * u + f11.x * wx) * wy;
    o.y = (f00.y * u + f10.y * wx) * v + (f01.y * u + f11.y * wx) * wy;

    // out[p, l*2 .. l*2+1] ; 16 consecutive threads -> 128B contiguous
    ((float2*)out)[(size_t)p * NLEV + l] = o;
}

extern "C" void kernel_launch(void* const* d_in, const int* in_sizes, int n_in,
                              void* d_out, int out_size)
{
    const float* x   = (const float*)d_in[0];
    const float* emb = (const float*)d_in[1];
    float* out       = (float*)d_out;

    int n_points = in_sizes[0] / 2;

    // Mirror numpy exactly: b = exp((log(512)-log(16))/15); res_l = floor(16 * b**l)
    // Host libm doubles, same machine/glibc as the reference's numpy.
    ResParams rp;
    double b = exp((log(512.0) - log(16.0)) / 15.0);
    for (int l = 0; l < NLEV; ++l) {
        rp.res[l] = (float)floor(16.0 * pow(b, (double)l));
    }

    long long total = (long long)n_points * NLEV;
    int threads = 256;
    int blocks = (int)((total + threads - 1) / threads);
    hash_embed_kernel<<<blocks, threads>>>(x, emb, out, n_points, rp);
}

// round 2
// speedup vs baseline: 1.2818x; 1.2818x over previous
#include <cuda_runtime.h>
#include <math.h>
#include <stdint.h>

// HashEmbedder: 16-level 2D multires hash grid, 2 feats/level, T=2^19.
// Two-phase: (1) build a cell-packed corner table (4 corner feats per cell,
// 32B contiguous), (2) per (point,level) do 2x LDG.128 + bilinear lerp.

#define NLEV 16
#define TLOG2 19
#define TSIZE (1u << TLOG2)
#define HMASK ((1u << TLOG2) - 1u)
#define PRIME1 2654435761u

// Sum of res^2 over the 16 levels = 706,816 cells; margin for safety.
#define MAX_CELLS 710000
__device__ float4 g_packed[2 * MAX_CELLS];

struct Params {
    float resF[NLEV];
    int   resI[NLEV];
    int   off[NLEV + 1];   // cell-table offset per level; off[16] = total
};

// ---------------------------------------------------------------------------
// Phase 1: build packed table. One thread per cell.
// packed[2*i]   = {f00.x, f00.y, f10.x, f10.y}
// packed[2*i+1] = {f01.x, f01.y, f11.x, f11.y}
// ---------------------------------------------------------------------------
__global__ __launch_bounds__(256) void build_packed_kernel(
    const float* __restrict__ emb, Params pm, int total_cells)
{
    int i = blockIdx.x * blockDim.x + threadIdx.x;
    if (i >= total_cells) return;

    int l = 0;
#pragma unroll
    for (int k = 1; k < NLEV; ++k) l += (i >= pm.off[k]);

    int c   = i - pm.off[l];
    int res = pm.resI[l];
    int cy  = c / res;
    int cx  = c - cy * res;

    // Corners (cx,cy),(cx+1,cy),(cx,cy+1),(cx+1,cy+1); all <= res, which is
    // exactly the reference's clip bound, so no clipping needed here.
    uint32_t ux0 = (uint32_t)cx;
    uint32_t ux1 = (uint32_t)(cx + 1);
    uint32_t yp0 = (uint32_t)cy * PRIME1;
    uint32_t yp1 = (uint32_t)(cy + 1) * PRIME1;

    uint32_t a00 = (ux0 ^ yp0) & HMASK;
    uint32_t a10 = (ux1 ^ yp0) & HMASK;
    uint32_t a01 = (ux0 ^ yp1) & HMASK;
    uint32_t a11 = (ux1 ^ yp1) & HMASK;

    const float2* __restrict__ tab =
        ((const float2*)emb) + ((size_t)l << TLOG2);

    float2 f00 = __ldg(tab + a00);
    float2 f10 = __ldg(tab + a10);
    float2 f01 = __ldg(tab + a01);
    float2 f11 = __ldg(tab + a11);

    g_packed[2 * i]     = make_float4(f00.x, f00.y, f10.x, f10.y);
    g_packed[2 * i + 1] = make_float4(f01.x, f01.y, f11.x, f11.y);
}

// ---------------------------------------------------------------------------
// Phase 2: main kernel. One thread per (point, level).
// ---------------------------------------------------------------------------
__global__ __launch_bounds__(256) void hash_embed_kernel(
    const float* __restrict__ x,
    float* __restrict__ out,
    int n_points,
    Params pm)
{
    __shared__ float s_resF[NLEV];
    __shared__ int   s_resI[NLEV];
    __shared__ int   s_off[NLEV];
    if (threadIdx.x < NLEV) {
        s_resF[threadIdx.x] = pm.resF[threadIdx.x];
        s_resI[threadIdx.x] = pm.resI[threadIdx.x];
        s_off[threadIdx.x]  = pm.off[threadIdx.x];
    }
    __syncthreads();

    int gid = blockIdx.x * blockDim.x + threadIdx.x;
    int p = gid >> 4;          // point index
    if (p >= n_points) return;
    int l = gid & 15;          // level index

    // 16 consecutive threads read the same point -> broadcast load
    float2 xy = __ldg(((const float2*)x) + p);

    float res = s_resF[l];
    int   ri  = s_resI[l];
    int   off = s_off[l];

    float px = xy.x * res;
    float py = xy.y * res;
    float fx = floorf(px);
    float fy = floorf(py);
    float wx = px - fx;
    float wy = py - fy;

    // x in [0,1) guarantees cell in [0, res-1]; clamp only for OOB safety.
    int ix = min(max((int)fx, 0), ri - 1);
    int iy = min(max((int)fy, 0), ri - 1);

    int idx = off + iy * ri + ix;

    float4 lo = __ldg(&g_packed[2 * idx]);      // f00, f10
    float4 hi = __ldg(&g_packed[2 * idx + 1]);  // f01, f11

    float u = 1.0f - wx;
    float v = 1.0f - wy;

    float2 o;
    o.x = (lo.x * u + lo.z * wx) * v + (hi.x * u + hi.z * wx) * wy;
    o.y = (lo.y * u + lo.w * wx) * v + (hi.y * u + hi.w * wx) * wy;

    // out[p, l*2 .. l*2+1] ; 16 consecutive threads -> 128B contiguous
    ((float2*)out)[(size_t)p * NLEV + l] = o;
}

extern "C" void kernel_launch(void* const* d_in, const int* in_sizes, int n_in,
                              void* d_out, int out_size)
{
    const float* x   = (const float*)d_in[0];
    const float* emb = (const float*)d_in[1];
    float* out       = (float*)d_out;

    int n_points = in_sizes[0] / 2;

    // Mirror numpy exactly: b = exp((log(512)-log(16))/15); res_l = floor(16*b^l)
    Params pm;
    double b = exp((log(512.0) - log(16.0)) / 15.0);
    int acc = 0;
    for (int l = 0; l < NLEV; ++l) {
        double r = floor(16.0 * pow(b, (double)l));
        pm.resF[l] = (float)r;
        pm.resI[l] = (int)r;
        pm.off[l]  = acc;
        acc += pm.resI[l] * pm.resI[l];
    }
    pm.off[NLEV] = acc;   // total cells (= 706816 for these constants)

    // Phase 1: build packed corner table
    {
        int threads = 256;
        int blocks = (acc + threads - 1) / threads;
        build_packed_kernel<<<blocks, threads>>>(emb, pm, acc);
    }

    // Phase 2: gather + lerp
    {
        long long total = (long long)n_points * NLEV;
        int threads = 256;
        int blocks = (int)((total + threads - 1) / threads);
        hash_embed_kernel<<<blocks, threads>>>(x, out, n_points, pm);
    }
}